// round 9
// baseline (speedup 1.0000x reference)
#include <cuda_runtime.h>
#include <math.h>

// Problem constants
#define Bn  4
#define Sn  2048
#define Dn  1024
#define Hn  16
#define HDn 64
#define TEn 64
#define Mn  (Bn * Sn)   // 8192

// ---------------------------------------------------------------------------
// Scratch (static device globals -- no allocation allowed in kernel_launch)
// ---------------------------------------------------------------------------
__device__ float g_q[Bn * Hn * Sn * HDn];      // [B,H,S,HD]
__device__ float g_k[Bn * Hn * Sn * HDn];
__device__ float g_v[Bn * Hn * Sn * HDn];
__device__ float g_attn[Bn * Sn * Dn];         // [B,S,H*HD] = [B,S,D]
__device__ float g_bias[Bn * Hn];

// ---------------------------------------------------------------------------
// Kernel 1: task bias  (B,TE) @ (TE,H) + bt -> (B,H)
// ---------------------------------------------------------------------------
__global__ void task_bias_kernel(const float* __restrict__ te,
                                 const float* __restrict__ Wt,
                                 const float* __restrict__ bt) {
    int t = threadIdx.x;
    if (t < Bn * Hn) {
        int b = t / Hn, h = t % Hn;
        float acc = bt[h];
        #pragma unroll 8
        for (int i = 0; i < TEn; i++) acc += te[b * TEn + i] * Wt[i * Hn + h];
        g_bias[t] = acc;
    }
}

// ---------------------------------------------------------------------------
// Kernel 2: fused QKV projection GEMM.
//   C = x @ W + b, result scattered to [B,H,S,HD] layout.
//   64x64 tile, BK=16, 256 threads, 4x4 register tile per thread.
//   blockIdx.z selects q / k / v.
// ---------------------------------------------------------------------------
__global__ __launch_bounds__(256)
void qkv_gemm_kernel(const float* __restrict__ x,
                     const float* __restrict__ Wq, const float* __restrict__ bq,
                     const float* __restrict__ Wk, const float* __restrict__ bk,
                     const float* __restrict__ Wv, const float* __restrict__ bv) {
    const float* W;
    const float* bias;
    float* out;
    if (blockIdx.z == 0)      { W = Wq; bias = bq; out = g_q; }
    else if (blockIdx.z == 1) { W = Wk; bias = bk; out = g_k; }
    else                      { W = Wv; bias = bv; out = g_v; }

    __shared__ float As[64][17];   // padded: kills ty-pair bank conflicts
    __shared__ float Ws[16][64];

    const int tid = threadIdx.x;
    const int tx  = tid & 15;
    const int ty  = tid >> 4;
    const int m0  = blockIdx.y * 64;
    const int n0  = blockIdx.x * 64;

    // load indices
    const int ar  = tid >> 2;          // A row   0..63
    const int ac4 = (tid & 3) * 4;     // A col4  0,4,8,12
    const int wr  = tid >> 4;          // W row   0..15
    const int wc4 = (tid & 15) * 4;    // W col4  0..60

    float acc[4][4] = {};

    for (int kk = 0; kk < Dn; kk += 16) {
        float4 av = *(const float4*)&x[(size_t)(m0 + ar) * Dn + kk + ac4];
        As[ar][ac4 + 0] = av.x; As[ar][ac4 + 1] = av.y;
        As[ar][ac4 + 2] = av.z; As[ar][ac4 + 3] = av.w;
        *(float4*)&Ws[wr][wc4] =
            *(const float4*)&W[(size_t)(kk + wr) * Dn + n0 + wc4];
        __syncthreads();

        #pragma unroll
        for (int k = 0; k < 16; k++) {
            float a0 = As[ty * 4 + 0][k];
            float a1 = As[ty * 4 + 1][k];
            float a2 = As[ty * 4 + 2][k];
            float a3 = As[ty * 4 + 3][k];
            float4 bv4 = *(const float4*)&Ws[k][tx * 4];
            acc[0][0] += a0 * bv4.x; acc[0][1] += a0 * bv4.y;
            acc[0][2] += a0 * bv4.z; acc[0][3] += a0 * bv4.w;
            acc[1][0] += a1 * bv4.x; acc[1][1] += a1 * bv4.y;
            acc[1][2] += a1 * bv4.z; acc[1][3] += a1 * bv4.w;
            acc[2][0] += a2 * bv4.x; acc[2][1] += a2 * bv4.y;
            acc[2][2] += a2 * bv4.z; acc[2][3] += a2 * bv4.w;
            acc[3][0] += a3 * bv4.x; acc[3][1] += a3 * bv4.y;
            acc[3][2] += a3 * bv4.z; acc[3][3] += a3 * bv4.w;
        }
        __syncthreads();
    }

    // epilogue: whole 64-wide tile belongs to one head (BN == HD)
    const int h = n0 >> 6;
    float4 bb = *(const float4*)&bias[n0 + tx * 4];
    #pragma unroll
    for (int i = 0; i < 4; i++) {
        int m = m0 + ty * 4 + i;
        int b = m >> 11;          // S = 2048 = 2^11
        int s = m & (Sn - 1);
        float4 o;
        o.x = acc[i][0] + bb.x; o.y = acc[i][1] + bb.y;
        o.z = acc[i][2] + bb.z; o.w = acc[i][3] + bb.w;
        *(float4*)&out[((size_t)((b * Hn + h) * Sn) + s) * HDn + tx * 4] = o;
    }
}

// ---------------------------------------------------------------------------
// Kernel 3: fused flash-style attention.
//   One block per (b, h, 64-row q tile). 256 threads (16x16), each owns a
//   4x4 sub-tile of the 64x64 score tile / 64x64 output tile.
//   Online softmax; per-row stats reduced over half-warps with shfl_xor.
// Dynamic smem layout:
//   Qs  [64][65]  (padded, scalar broadcast reads)
//   KsT [64][68]  (K transposed: KsT[d][kcol], float4 conflict-free reads)
//   Vs  [64][64]  (natural layout, float4 reads)
//   Ps  [64][65]
// ---------------------------------------------------------------------------
#define QS_STRIDE 65
#define KT_STRIDE 68
#define PS_STRIDE 65
#define ATTN_SMEM_FLOATS (64 * QS_STRIDE + 64 * KT_STRIDE + 64 * 64 + 64 * PS_STRIDE)
#define ATTN_SMEM_BYTES  (ATTN_SMEM_FLOATS * 4)

__global__ __launch_bounds__(256)
void attn_kernel(const int* __restrict__ mask) {
    extern __shared__ float sm[];
    float* Qs  = sm;                          // 64*65
    float* KsT = Qs  + 64 * QS_STRIDE;        // 64*68
    float* Vs  = KsT + 64 * KT_STRIDE;        // 64*64
    float* Ps  = Vs  + 64 * 64;               // 64*65
    __shared__ int maskS[64];

    const int tid = threadIdx.x;
    const int tx  = tid & 15;
    const int ty  = tid >> 4;
    const int q0  = blockIdx.x * 64;
    const int h   = blockIdx.y;
    const int b   = blockIdx.z;

    const float* qbase = g_q + ((size_t)(b * Hn + h) * Sn + q0) * HDn;
    const float* kbase = g_k + ((size_t)(b * Hn + h) * Sn) * HDn;
    const float* vbase = g_v + ((size_t)(b * Hn + h) * Sn) * HDn;
    const float bias   = g_bias[b * Hn + h];
    const float scale  = 0.125f;   // HD^-0.5

    // ---- load Q tile once (64x64 contiguous) ----
    #pragma unroll
    for (int it = 0; it < 4; it++) {
        int lin = tid + it * 256;             // float4 index 0..1023
        int row = lin >> 4;
        int c4  = (lin & 15) * 4;
        float4 v = ((const float4*)qbase)[lin];
        Qs[row * QS_STRIDE + c4 + 0] = v.x;
        Qs[row * QS_STRIDE + c4 + 1] = v.y;
        Qs[row * QS_STRIDE + c4 + 2] = v.z;
        Qs[row * QS_STRIDE + c4 + 3] = v.w;
    }

    float m_i[4], l_i[4], o_acc[4][4];
    #pragma unroll
    for (int i = 0; i < 4; i++) {
        m_i[i] = -1e30f; l_i[i] = 0.0f;
        #pragma unroll
        for (int j = 0; j < 4; j++) o_acc[i][j] = 0.0f;
    }

    for (int kt = 0; kt < Sn / 64; kt++) {
        const int k0 = kt * 64;
        __syncthreads();   // previous iteration's P@V must finish before overwrite

        // ---- load K (transposed) and V tiles + mask slice ----
        #pragma unroll
        for (int it = 0; it < 4; it++) {
            int lin = tid + it * 256;
            int row = lin >> 4;
            int c4  = (lin & 15) * 4;
            float4 kv = ((const float4*)(kbase + (size_t)k0 * HDn))[lin];
            KsT[(c4 + 0) * KT_STRIDE + row] = kv.x;
            KsT[(c4 + 1) * KT_STRIDE + row] = kv.y;
            KsT[(c4 + 2) * KT_STRIDE + row] = kv.z;
            KsT[(c4 + 3) * KT_STRIDE + row] = kv.w;
            ((float4*)Vs)[lin] = ((const float4*)(vbase + (size_t)k0 * HDn))[lin];
        }
        if (tid < 64) maskS[tid] = mask[b * Sn + k0 + tid];
        __syncthreads();

        // ---- S = Q @ K^T (4x4 per thread) ----
        float s[4][4] = {};
        #pragma unroll
        for (int d = 0; d < 64; d++) {
            float a0 = Qs[(ty * 4 + 0) * QS_STRIDE + d];
            float a1 = Qs[(ty * 4 + 1) * QS_STRIDE + d];
            float a2 = Qs[(ty * 4 + 2) * QS_STRIDE + d];
            float a3 = Qs[(ty * 4 + 3) * QS_STRIDE + d];
            float4 kd = *(const float4*)&KsT[d * KT_STRIDE + tx * 4];
            s[0][0] += a0 * kd.x; s[0][1] += a0 * kd.y;
            s[0][2] += a0 * kd.z; s[0][3] += a0 * kd.w;
            s[1][0] += a1 * kd.x; s[1][1] += a1 * kd.y;
            s[1][2] += a1 * kd.z; s[1][3] += a1 * kd.w;
            s[2][0] += a2 * kd.x; s[2][1] += a2 * kd.y;
            s[2][2] += a2 * kd.z; s[2][3] += a2 * kd.w;
            s[3][0] += a3 * kd.x; s[3][1] += a3 * kd.y;
            s[3][2] += a3 * kd.z; s[3][3] += a3 * kd.w;
        }

        int mk0 = maskS[tx * 4 + 0], mk1 = maskS[tx * 4 + 1];
        int mk2 = maskS[tx * 4 + 2], mk3 = maskS[tx * 4 + 3];
        #pragma unroll
        for (int i = 0; i < 4; i++) {
            s[i][0] = mk0 ? s[i][0] * scale + bias : -1e30f;
            s[i][1] = mk1 ? s[i][1] * scale + bias : -1e30f;
            s[i][2] = mk2 ? s[i][2] * scale + bias : -1e30f;
            s[i][3] = mk3 ? s[i][3] * scale + bias : -1e30f;
        }

        // ---- online softmax per row (16-lane half-warp owns a row group) ----
        #pragma unroll
        for (int i = 0; i < 4; i++) {
            float mx = fmaxf(fmaxf(s[i][0], s[i][1]), fmaxf(s[i][2], s[i][3]));
            #pragma unroll
            for (int off = 8; off >= 1; off >>= 1)
                mx = fmaxf(mx, __shfl_xor_sync(0xffffffffu, mx, off));
            float m_new = fmaxf(m_i[i], mx);
            float p0 = __expf(s[i][0] - m_new);
            float p1 = __expf(s[i][1] - m_new);
            float p2 = __expf(s[i][2] - m_new);
            float p3 = __expf(s[i][3] - m_new);
            float rs = p0 + p1 + p2 + p3;
            #pragma unroll
            for (int off = 8; off >= 1; off >>= 1)
                rs += __shfl_xor_sync(0xffffffffu, rs, off);
            float alpha = __expf(m_i[i] - m_new);
            l_i[i] = l_i[i] * alpha + rs;
            m_i[i] = m_new;
            #pragma unroll
            for (int j = 0; j < 4; j++) o_acc[i][j] *= alpha;
            int prow = (ty * 4 + i) * PS_STRIDE + tx * 4;
            Ps[prow + 0] = p0; Ps[prow + 1] = p1;
            Ps[prow + 2] = p2; Ps[prow + 3] = p3;
        }
        __syncthreads();

        // ---- O += P @ V ----
        #pragma unroll
        for (int k = 0; k < 64; k++) {
            float p0 = Ps[(ty * 4 + 0) * PS_STRIDE + k];
            float p1 = Ps[(ty * 4 + 1) * PS_STRIDE + k];
            float p2 = Ps[(ty * 4 + 2) * PS_STRIDE + k];
            float p3 = Ps[(ty * 4 + 3) * PS_STRIDE + k];
            float4 vv = *(const float4*)&Vs[k * 64 + tx * 4];
            o_acc[0][0] += p0 * vv.x; o_acc[0][1] += p0 * vv.y;
            o_acc[0][2] += p0 * vv.z; o_acc[0][3] += p0 * vv.w;
            o_acc[1][0] += p1 * vv.x; o_acc[1][1] += p1 * vv.y;
            o_acc[1][2] += p1 * vv.z; o_acc[1][3] += p1 * vv.w;
            o_acc[2][0] += p2 * vv.x; o_acc[2][1] += p2 * vv.y;
            o_acc[2][2] += p2 * vv.z; o_acc[2][3] += p2 * vv.w;
            o_acc[3][0] += p3 * vv.x; o_acc[3][1] += p3 * vv.y;
            o_acc[3][2] += p3 * vv.z; o_acc[3][3] += p3 * vv.w;
        }
    }

    // ---- finalize and write [B,S,H*HD] ----
    #pragma unroll
    for (int i = 0; i < 4; i++) {
        float inv = 1.0f / l_i[i];
        int q = q0 + ty * 4 + i;
        float4 o;
        o.x = o_acc[i][0] * inv; o.y = o_acc[i][1] * inv;
        o.z = o_acc[i][2] * inv; o.w = o_acc[i][3] * inv;
        *(float4*)&g_attn[((size_t)(b * Sn + q)) * Dn + h * HDn + tx * 4] = o;
    }
}

// ---------------------------------------------------------------------------
// Kernel 4: output projection GEMM: out = g_attn @ Wo + bo, plain [M,N].
// ---------------------------------------------------------------------------
__global__ __launch_bounds__(256)
void out_gemm_kernel(const float* __restrict__ Wo,
                     const float* __restrict__ bo,
                     float* __restrict__ out) {
    __shared__ float As[64][17];
    __shared__ float Ws[16][64];

    const int tid = threadIdx.x;
    const int tx  = tid & 15;
    const int ty  = tid >> 4;
    const int m0  = blockIdx.y * 64;
    const int n0  = blockIdx.x * 64;

    const int ar  = tid >> 2;
    const int ac4 = (tid & 3) * 4;
    const int wr  = tid >> 4;
    const int wc4 = (tid & 15) * 4;

    float acc[4][4] = {};

    for (int kk = 0; kk < Dn; kk += 16) {
        float4 av = *(const float4*)&g_attn[(size_t)(m0 + ar) * Dn + kk + ac4];
        As[ar][ac4 + 0] = av.x; As[ar][ac4 + 1] = av.y;
        As[ar][ac4 + 2] = av.z; As[ar][ac4 + 3] = av.w;
        *(float4*)&Ws[wr][wc4] =
            *(const float4*)&Wo[(size_t)(kk + wr) * Dn + n0 + wc4];
        __syncthreads();

        #pragma unroll
        for (int k = 0; k < 16; k++) {
            float a0 = As[ty * 4 + 0][k];
            float a1 = As[ty * 4 + 1][k];
            float a2 = As[ty * 4 + 2][k];
            float a3 = As[ty * 4 + 3][k];
            float4 bv4 = *(const float4*)&Ws[k][tx * 4];
            acc[0][0] += a0 * bv4.x; acc[0][1] += a0 * bv4.y;
            acc[0][2] += a0 * bv4.z; acc[0][3] += a0 * bv4.w;
            acc[1][0] += a1 * bv4.x; acc[1][1] += a1 * bv4.y;
            acc[1][2] += a1 * bv4.z; acc[1][3] += a1 * bv4.w;
            acc[2][0] += a2 * bv4.x; acc[2][1] += a2 * bv4.y;
            acc[2][2] += a2 * bv4.z; acc[2][3] += a2 * bv4.w;
            acc[3][0] += a3 * bv4.x; acc[3][1] += a3 * bv4.y;
            acc[3][2] += a3 * bv4.z; acc[3][3] += a3 * bv4.w;
        }
        __syncthreads();
    }

    float4 bb = *(const float4*)&bo[n0 + tx * 4];
    #pragma unroll
    for (int i = 0; i < 4; i++) {
        int m = m0 + ty * 4 + i;
        float4 o;
        o.x = acc[i][0] + bb.x; o.y = acc[i][1] + bb.y;
        o.z = acc[i][2] + bb.z; o.w = acc[i][3] + bb.w;
        *(float4*)&out[(size_t)m * Dn + n0 + tx * 4] = o;
    }
}

// ---------------------------------------------------------------------------
// Launch
// ---------------------------------------------------------------------------
extern "C" void kernel_launch(void* const* d_in, const int* in_sizes, int n_in,
                              void* d_out, int out_size) {
    const float* x    = (const float*)d_in[0];
    const float* te   = (const float*)d_in[1];
    const int*   mask = (const int*)  d_in[2];
    const float* Wq   = (const float*)d_in[3];
    const float* bq   = (const float*)d_in[4];
    const float* Wk   = (const float*)d_in[5];
    const float* bk   = (const float*)d_in[6];
    const float* Wv   = (const float*)d_in[7];
    const float* bv   = (const float*)d_in[8];
    const float* Wo   = (const float*)d_in[9];
    const float* bo   = (const float*)d_in[10];
    const float* Wt   = (const float*)d_in[11];
    const float* bt   = (const float*)d_in[12];
    float* out = (float*)d_out;

    (void)in_sizes; (void)n_in; (void)out_size;

    cudaFuncSetAttribute(attn_kernel,
                         cudaFuncAttributeMaxDynamicSharedMemorySize,
                         ATTN_SMEM_BYTES);

    task_bias_kernel<<<1, 64>>>(te, Wt, bt);
    qkv_gemm_kernel<<<dim3(Dn / 64, Mn / 64, 3), 256>>>(x, Wq, bq, Wk, bk, Wv, bv);
    attn_kernel<<<dim3(Sn / 64, Hn, Bn), 256, ATTN_SMEM_BYTES>>>(mask);
    out_gemm_kernel<<<dim3(Dn / 64, Mn / 64, 1), 256>>>(Wo, bo, out);
}

// round 10
// speedup vs baseline: 3.1785x; 3.1785x over previous
#include <cuda_runtime.h>
#include <math.h>
#include <stdint.h>

// Problem constants
#define Bn  4
#define Sn  2048
#define Dn  1024
#define Hn  16
#define HDn 64
#define TEn 64
#define Mn  (Bn * Sn)   // 8192

// ---------------------------------------------------------------------------
// Scratch
// ---------------------------------------------------------------------------
__device__ float g_q[Bn * Hn * Sn * HDn];      // [B,H,S,HD]
__device__ float g_k[Bn * Hn * Sn * HDn];
__device__ float g_v[Bn * Hn * Sn * HDn];
__device__ float g_attn[Bn * Sn * Dn];         // [B,S,D]
__device__ float g_bias[Bn * Hn];

// ---------------------------------------------------------------------------
// PTX helpers
// ---------------------------------------------------------------------------
__device__ __forceinline__ uint32_t f2tf32(float f) {
    uint32_t u;
    asm("cvt.rna.tf32.f32 %0, %1;" : "=r"(u) : "f"(f));
    return u;
}

__device__ __forceinline__ void mma_tf32(float c[4],
                                         uint32_t a0, uint32_t a1, uint32_t a2, uint32_t a3,
                                         uint32_t b0, uint32_t b1) {
    asm volatile(
        "mma.sync.aligned.m16n8k8.row.col.f32.tf32.tf32.f32 "
        "{%0,%1,%2,%3}, {%4,%5,%6,%7}, {%8,%9}, {%0,%1,%2,%3};"
        : "+f"(c[0]), "+f"(c[1]), "+f"(c[2]), "+f"(c[3])
        : "r"(a0), "r"(a1), "r"(a2), "r"(a3), "r"(b0), "r"(b1));
}

__device__ __forceinline__ void ldm_x4(uint32_t r[4], const float* p) {
    uint32_t addr = (uint32_t)__cvta_generic_to_shared(p);
    asm volatile("ldmatrix.sync.aligned.m8n8.x4.shared.b16 {%0,%1,%2,%3}, [%4];"
                 : "=r"(r[0]), "=r"(r[1]), "=r"(r[2]), "=r"(r[3])
                 : "r"(addr));
}

// ---------------------------------------------------------------------------
// Kernel 1: task bias  (B,TE) @ (TE,H) + bt -> (B,H)
// ---------------------------------------------------------------------------
__global__ void task_bias_kernel(const float* __restrict__ te,
                                 const float* __restrict__ Wt,
                                 const float* __restrict__ bt) {
    int t = threadIdx.x;
    if (t < Bn * Hn) {
        int b = t / Hn, h = t % Hn;
        float acc = bt[h];
        #pragma unroll 8
        for (int i = 0; i < TEn; i++) acc += te[b * TEn + i] * Wt[i * Hn + h];
        g_bias[t] = acc;
    }
}

// ---------------------------------------------------------------------------
// tf32 tensor-core GEMM body: C = A(M,K) @ W(K,N) + bias
// BM=128, BN=128, BK=32, 256 threads = 8 warps (4M x 2N), warp tile 32x64.
// SCATTER=1 remaps output rows/cols to [B,H,S,HD].
// ---------------------------------------------------------------------------
#define AS_ST 36     // A smem stride (floats); 144B rows -> ldmatrix conflict-free
#define BS_ST 136    // B smem stride; 136 % 32 == 8 -> conflict-free B-frag LDS

template<int SCATTER>
__device__ __forceinline__ void gemm_tf32_body(
    const float* __restrict__ A, const float* __restrict__ W,
    const float* __restrict__ bias, float* __restrict__ out)
{
    __shared__ float As[128 * AS_ST];
    __shared__ float Bs[32 * BS_ST];

    const int tid  = threadIdx.x;
    const int lane = tid & 31;
    const int warp = tid >> 5;
    const int wm   = warp & 3;       // 0..3  (M)
    const int wn   = warp >> 2;      // 0..1  (N)
    const int m0   = blockIdx.y * 128;
    const int n0   = blockIdx.x * 128;

    const int arow = (lane < 16) ? lane : lane - 16;
    const int acol = (lane < 16) ? 0 : 4;
    const int lk   = lane & 3;
    const int ln   = lane >> 2;

    float acc[2][8][4] = {};

    for (int kk = 0; kk < Dn; kk += 32) {
        // A tile 128x32 -> As (tf32)
        #pragma unroll
        for (int i = 0; i < 4; i++) {
            int lin = tid + i * 256;
            int r = lin >> 3, c4 = (lin & 7) << 2;
            float4 v = *(const float4*)&A[(size_t)(m0 + r) * Dn + kk + c4];
            uint32_t* dst = (uint32_t*)&As[r * AS_ST + c4];
            dst[0] = f2tf32(v.x); dst[1] = f2tf32(v.y);
            dst[2] = f2tf32(v.z); dst[3] = f2tf32(v.w);
        }
        // W tile 32x128 -> Bs (tf32)
        #pragma unroll
        for (int i = 0; i < 4; i++) {
            int lin = tid + i * 256;
            int r = lin >> 5, c4 = (lin & 31) << 2;
            float4 v = *(const float4*)&W[(size_t)(kk + r) * Dn + n0 + c4];
            uint32_t* dst = (uint32_t*)&Bs[r * BS_ST + c4];
            dst[0] = f2tf32(v.x); dst[1] = f2tf32(v.y);
            dst[2] = f2tf32(v.z); dst[3] = f2tf32(v.w);
        }
        __syncthreads();

        #pragma unroll
        for (int ks = 0; ks < 4; ks++) {
            const int k0 = ks * 8;
            uint32_t af[2][4];
            #pragma unroll
            for (int mi = 0; mi < 2; mi++)
                ldm_x4(af[mi], &As[(wm * 32 + mi * 16 + arow) * AS_ST + k0 + acol]);
            uint32_t bf0[8], bf1[8];
            #pragma unroll
            for (int ni = 0; ni < 8; ni++) {
                int n = wn * 64 + ni * 8 + ln;
                bf0[ni] = __float_as_uint(Bs[(k0 + lk)     * BS_ST + n]);
                bf1[ni] = __float_as_uint(Bs[(k0 + 4 + lk) * BS_ST + n]);
            }
            #pragma unroll
            for (int mi = 0; mi < 2; mi++)
                #pragma unroll
                for (int ni = 0; ni < 8; ni++)
                    mma_tf32(acc[mi][ni], af[mi][0], af[mi][1], af[mi][2], af[mi][3],
                             bf0[ni], bf1[ni]);
        }
        __syncthreads();
    }

    // epilogue
    #pragma unroll
    for (int mi = 0; mi < 2; mi++) {
        #pragma unroll
        for (int ni = 0; ni < 8; ni++) {
            int n = n0 + wn * 64 + ni * 8 + lk * 2;
            float bb0 = bias[n], bb1 = bias[n + 1];
            #pragma unroll
            for (int rr = 0; rr < 2; rr++) {
                int m = m0 + wm * 32 + mi * 16 + ln + rr * 8;
                float2 o;
                o.x = acc[mi][ni][rr * 2 + 0] + bb0;
                o.y = acc[mi][ni][rr * 2 + 1] + bb1;
                if (SCATTER) {
                    int b = m >> 11, s = m & (Sn - 1);
                    int h = n >> 6, hd = n & 63;
                    *(float2*)&out[((size_t)(b * Hn + h) * Sn + s) * HDn + hd] = o;
                } else {
                    *(float2*)&out[(size_t)m * Dn + n] = o;
                }
            }
        }
    }
}

__global__ __launch_bounds__(256, 2)
void qkv_gemm_tc_kernel(const float* __restrict__ x,
                        const float* __restrict__ Wq, const float* __restrict__ bq,
                        const float* __restrict__ Wk, const float* __restrict__ bk,
                        const float* __restrict__ Wv, const float* __restrict__ bv) {
    const float* W; const float* bias; float* out;
    if (blockIdx.z == 0)      { W = Wq; bias = bq; out = g_q; }
    else if (blockIdx.z == 1) { W = Wk; bias = bk; out = g_k; }
    else                      { W = Wv; bias = bv; out = g_v; }
    gemm_tf32_body<1>(x, W, bias, out);
}

__global__ __launch_bounds__(256, 2)
void out_gemm_tc_kernel(const float* __restrict__ Wo,
                        const float* __restrict__ bo,
                        float* __restrict__ out) {
    gemm_tf32_body<0>(g_attn, Wo, bo, out);
}

// ---------------------------------------------------------------------------
// Kernel 3: tensor-core flash attention.
// 64 q-rows per block, 4 warps (warp w owns rows w*16..w*16+15).
// Smem: Qs [64][68] (recycled as Ps after Q fragments are register-resident),
//       Ks [64][68] (natural [key][hd]; B-frag LDS conflict-free),
//       Vs [64][72] (natural [key][hd]; stride 72 -> conflict-free B-frag LDS).
// ---------------------------------------------------------------------------
#define QP_ST 68
#define VS_ST 72
#define ATTN_SMEM_FLOATS (64 * QP_ST * 2 + 64 * VS_ST)
#define ATTN_SMEM_BYTES  (ATTN_SMEM_FLOATS * 4)

__global__ __launch_bounds__(128)
void attn_tc_kernel(const int* __restrict__ mask) {
    extern __shared__ float sm[];
    float* Qs = sm;                     // 64*68, later Ps
    float* Ks = sm + 64 * QP_ST;        // 64*68
    float* Vs = sm + 2 * 64 * QP_ST;    // 64*72
    __shared__ int maskS[64];

    const int tid  = threadIdx.x;
    const int lane = tid & 31;
    const int warp = tid >> 5;
    const int q0   = blockIdx.x * 64;
    const int h    = blockIdx.y;
    const int b    = blockIdx.z;

    const float* qb = g_q + ((size_t)(b * Hn + h) * Sn + q0) * HDn;
    const float* kb = g_k + ((size_t)(b * Hn + h) * Sn) * HDn;
    const float* vb = g_v + ((size_t)(b * Hn + h) * Sn) * HDn;
    const float bias  = g_bias[b * Hn + h];
    const float scale = 0.125f;

    const int arow = (lane < 16) ? lane : lane - 16;
    const int acol = (lane < 16) ? 0 : 4;
    const int lk   = lane & 3;
    const int ln   = lane >> 2;

    // ---- load Q tile (64x64), tf32 ----
    #pragma unroll
    for (int i = 0; i < 8; i++) {
        int lin = tid + i * 128;
        int r = lin >> 4, c4 = (lin & 15) << 2;
        float4 v = ((const float4*)qb)[lin];
        uint32_t* dst = (uint32_t*)&Qs[r * QP_ST + c4];
        dst[0] = f2tf32(v.x); dst[1] = f2tf32(v.y);
        dst[2] = f2tf32(v.z); dst[3] = f2tf32(v.w);
    }
    __syncthreads();

    // ---- Q fragments -> registers (held for whole kernel) ----
    uint32_t qf[8][4];
    #pragma unroll
    for (int ks = 0; ks < 8; ks++)
        ldm_x4(qf[ks], &Qs[(warp * 16 + arow) * QP_ST + ks * 8 + acol]);
    __syncthreads();   // everyone done reading Qs; Qs becomes Ps

    float o[8][4] = {};
    float m_i[2] = {-1e30f, -1e30f};
    float l_i[2] = {0.0f, 0.0f};

    for (int kt = 0; kt < Sn / 64; kt++) {
        const int k0 = kt * 64;
        __syncthreads();   // all warps done with previous Ks/Vs

        // ---- load K, V tiles (tf32) + mask slice ----
        #pragma unroll
        for (int i = 0; i < 8; i++) {
            int lin = tid + i * 128;
            int r = lin >> 4, c4 = (lin & 15) << 2;
            float4 kv = ((const float4*)(kb + (size_t)k0 * HDn))[lin];
            uint32_t* kd = (uint32_t*)&Ks[r * QP_ST + c4];
            kd[0] = f2tf32(kv.x); kd[1] = f2tf32(kv.y);
            kd[2] = f2tf32(kv.z); kd[3] = f2tf32(kv.w);
            float4 vv = ((const float4*)(vb + (size_t)k0 * HDn))[lin];
            uint32_t* vd = (uint32_t*)&Vs[r * VS_ST + c4];
            vd[0] = f2tf32(vv.x); vd[1] = f2tf32(vv.y);
            vd[2] = f2tf32(vv.z); vd[3] = f2tf32(vv.w);
        }
        if (tid < 64) maskS[tid] = mask[b * Sn + k0 + tid];
        __syncthreads();

        // ---- S = Q @ K^T   (m16 q rows x n64 keys, k = hd 64) ----
        float sacc[8][4] = {};
        #pragma unroll
        for (int ks = 0; ks < 8; ks++) {
            #pragma unroll
            for (int ni = 0; ni < 8; ni++) {
                uint32_t b0 = __float_as_uint(Ks[(ni * 8 + ln) * QP_ST + ks * 8 + lk]);
                uint32_t b1 = __float_as_uint(Ks[(ni * 8 + ln) * QP_ST + ks * 8 + 4 + lk]);
                mma_tf32(sacc[ni], qf[ks][0], qf[ks][1], qf[ks][2], qf[ks][3], b0, b1);
            }
        }

        // ---- online softmax on C-fragments; write P (tf32) into Ps ----
        #pragma unroll
        for (int rr = 0; rr < 2; rr++) {
            float sv[8][2];
            float mx = -1e30f;
            #pragma unroll
            for (int ni = 0; ni < 8; ni++) {
                int c = ni * 8 + lk * 2;
                float s0 = maskS[c]     ? sacc[ni][rr * 2 + 0] * scale + bias : -1e30f;
                float s1 = maskS[c + 1] ? sacc[ni][rr * 2 + 1] * scale + bias : -1e30f;
                sv[ni][0] = s0; sv[ni][1] = s1;
                mx = fmaxf(mx, fmaxf(s0, s1));
            }
            mx = fmaxf(mx, __shfl_xor_sync(0xffffffffu, mx, 1));
            mx = fmaxf(mx, __shfl_xor_sync(0xffffffffu, mx, 2));
            float m_new = fmaxf(m_i[rr], mx);

            float rs = 0.0f;
            int prow = (warp * 16 + ln + rr * 8) * QP_ST;
            #pragma unroll
            for (int ni = 0; ni < 8; ni++) {
                float p0 = __expf(sv[ni][0] - m_new);
                float p1 = __expf(sv[ni][1] - m_new);
                rs += p0 + p1;
                float2 pp;
                pp.x = __uint_as_float(f2tf32(p0));
                pp.y = __uint_as_float(f2tf32(p1));
                *(float2*)&Qs[prow + ni * 8 + lk * 2] = pp;
            }
            rs += __shfl_xor_sync(0xffffffffu, rs, 1);
            rs += __shfl_xor_sync(0xffffffffu, rs, 2);

            float alpha = __expf(m_i[rr] - m_new);
            l_i[rr] = l_i[rr] * alpha + rs;
            m_i[rr] = m_new;
            #pragma unroll
            for (int ni = 0; ni < 8; ni++) {
                o[ni][rr * 2 + 0] *= alpha;
                o[ni][rr * 2 + 1] *= alpha;
            }
        }
        __syncwarp();   // P rows are per-warp private; make STS visible to ldmatrix

        // ---- O += P @ V   (m16 q rows x n64 hd, k = 64 keys) ----
        #pragma unroll
        for (int ks = 0; ks < 8; ks++) {
            uint32_t pf[4];
            ldm_x4(pf, &Qs[(warp * 16 + arow) * QP_ST + ks * 8 + acol]);
            #pragma unroll
            for (int ni = 0; ni < 8; ni++) {
                uint32_t b0 = __float_as_uint(Vs[(ks * 8 + lk)     * VS_ST + ni * 8 + ln]);
                uint32_t b1 = __float_as_uint(Vs[(ks * 8 + 4 + lk) * VS_ST + ni * 8 + ln]);
                mma_tf32(o[ni], pf[0], pf[1], pf[2], pf[3], b0, b1);
            }
        }
    }

    // ---- finalize, write [B,S,D] ----
    #pragma unroll
    for (int rr = 0; rr < 2; rr++) {
        float inv = 1.0f / l_i[rr];
        int q = q0 + warp * 16 + ln + rr * 8;
        #pragma unroll
        for (int ni = 0; ni < 8; ni++) {
            float2 ov;
            ov.x = o[ni][rr * 2 + 0] * inv;
            ov.y = o[ni][rr * 2 + 1] * inv;
            *(float2*)&g_attn[((size_t)(b * Sn + q)) * Dn + h * HDn + ni * 8 + lk * 2] = ov;
        }
    }
}

// ---------------------------------------------------------------------------
// Launch
// ---------------------------------------------------------------------------
extern "C" void kernel_launch(void* const* d_in, const int* in_sizes, int n_in,
                              void* d_out, int out_size) {
    const float* x    = (const float*)d_in[0];
    const float* te   = (const float*)d_in[1];
    const int*   mask = (const int*)  d_in[2];
    const float* Wq   = (const float*)d_in[3];
    const float* bq   = (const float*)d_in[4];
    const float* Wk   = (const float*)d_in[5];
    const float* bk   = (const float*)d_in[6];
    const float* Wv   = (const float*)d_in[7];
    const float* bv   = (const float*)d_in[8];
    const float* Wo   = (const float*)d_in[9];
    const float* bo   = (const float*)d_in[10];
    const float* Wt   = (const float*)d_in[11];
    const float* bt   = (const float*)d_in[12];
    float* out = (float*)d_out;

    (void)in_sizes; (void)n_in; (void)out_size;

    cudaFuncSetAttribute(attn_tc_kernel,
                         cudaFuncAttributeMaxDynamicSharedMemorySize,
                         ATTN_SMEM_BYTES);

    task_bias_kernel<<<1, 64>>>(te, Wt, bt);
    qkv_gemm_tc_kernel<<<dim3(Dn / 128, Mn / 128, 3), 256>>>(x, Wq, bq, Wk, bk, Wv, bv);
    attn_tc_kernel<<<dim3(Sn / 64, Hn, Bn), 128, ATTN_SMEM_BYTES>>>(mask);
    out_gemm_tc_kernel<<<dim3(Dn / 128, Mn / 128, 1), 256>>>(Wo, bo, out);
}

// round 11
// speedup vs baseline: 3.4277x; 1.0784x over previous
#include <cuda_runtime.h>
#include <math.h>
#include <stdint.h>

// Problem constants
#define Bn  4
#define Sn  2048
#define Dn  1024
#define Hn  16
#define HDn 64
#define TEn 64
#define Mn  (Bn * Sn)   // 8192

// ---------------------------------------------------------------------------
// Scratch
// ---------------------------------------------------------------------------
__device__ float g_q[Bn * Hn * Sn * HDn];      // [B,H,S,HD]
__device__ float g_k[Bn * Hn * Sn * HDn];
__device__ float g_v[Bn * Hn * Sn * HDn];
__device__ float g_attn[Bn * Sn * Dn];         // [B,S,D]
__device__ float g_bias[Bn * Hn];

// ---------------------------------------------------------------------------
// PTX helpers
// ---------------------------------------------------------------------------
__device__ __forceinline__ uint32_t f2tf32(float f) {
    uint32_t u;
    asm("cvt.rna.tf32.f32 %0, %1;" : "=r"(u) : "f"(f));
    return u;
}
__device__ __forceinline__ uint32_t u2tf32(uint32_t x) {
    uint32_t y;
    asm("cvt.rna.tf32.f32 %0, %1;" : "=r"(y) : "f"(__uint_as_float(x)));
    return y;
}

__device__ __forceinline__ void mma_tf32(float c[4],
                                         uint32_t a0, uint32_t a1, uint32_t a2, uint32_t a3,
                                         uint32_t b0, uint32_t b1) {
    asm volatile(
        "mma.sync.aligned.m16n8k8.row.col.f32.tf32.tf32.f32 "
        "{%0,%1,%2,%3}, {%4,%5,%6,%7}, {%8,%9}, {%0,%1,%2,%3};"
        : "+f"(c[0]), "+f"(c[1]), "+f"(c[2]), "+f"(c[3])
        : "r"(a0), "r"(a1), "r"(a2), "r"(a3), "r"(b0), "r"(b1));
}

__device__ __forceinline__ void ldm_x4(uint32_t r[4], const float* p) {
    uint32_t addr = (uint32_t)__cvta_generic_to_shared(p);
    asm volatile("ldmatrix.sync.aligned.m8n8.x4.shared.b16 {%0,%1,%2,%3}, [%4];"
                 : "=r"(r[0]), "=r"(r[1]), "=r"(r[2]), "=r"(r[3])
                 : "r"(addr));
}

__device__ __forceinline__ void cp16(float* dst, const float* src) {
    uint32_t d = (uint32_t)__cvta_generic_to_shared(dst);
    asm volatile("cp.async.cg.shared.global [%0], [%1], 16;" :: "r"(d), "l"(src));
}
__device__ __forceinline__ void cp_commit() {
    asm volatile("cp.async.commit_group;" ::: "memory");
}
template<int N>
__device__ __forceinline__ void cp_wait() {
    asm volatile("cp.async.wait_group %0;" :: "n"(N) : "memory");
}

// ---------------------------------------------------------------------------
// Kernel 1: task bias  (B,TE) @ (TE,H) + bt -> (B,H)
// ---------------------------------------------------------------------------
__global__ void task_bias_kernel(const float* __restrict__ te,
                                 const float* __restrict__ Wt,
                                 const float* __restrict__ bt) {
    int t = threadIdx.x;
    if (t < Bn * Hn) {
        int b = t / Hn, h = t % Hn;
        float acc = bt[h];
        #pragma unroll 8
        for (int i = 0; i < TEn; i++) acc += te[b * TEn + i] * Wt[i * Hn + h];
        g_bias[t] = acc;
    }
}

// ---------------------------------------------------------------------------
// tf32 tensor-core GEMM, cp.async double-buffered.
// BM=128, BN=128, BK=32, 256 threads = 8 warps (4M x 2N), warp tile 32x64.
// Raw fp32 in smem; tf32 conversion happens on register fragments.
// ---------------------------------------------------------------------------
#define AS_ST 36     // A smem stride (floats); 144B rows, 16B aligned
#define BS_ST 136    // B smem stride; 136 % 32 == 8 -> conflict-free B-frag LDS

template<int SCATTER>
__device__ __forceinline__ void gemm_tf32_body(
    const float* __restrict__ A, const float* __restrict__ W,
    const float* __restrict__ bias, float* __restrict__ out)
{
    __shared__ float As[2][128 * AS_ST];
    __shared__ float Bs[2][32 * BS_ST];

    const int tid  = threadIdx.x;
    const int lane = tid & 31;
    const int warp = tid >> 5;
    const int wm   = warp & 3;
    const int wn   = warp >> 2;
    const int m0   = blockIdx.y * 128;
    const int n0   = blockIdx.x * 128;

    const int arow = (lane < 16) ? lane : lane - 16;
    const int acol = (lane < 16) ? 0 : 4;
    const int lk   = lane & 3;
    const int ln   = lane >> 2;

    float acc[2][8][4] = {};

    const int NK = Dn / 32;   // 32 k-steps

    auto issue = [&](int kk, int s) {
        #pragma unroll
        for (int i = 0; i < 4; i++) {
            int lin = tid + i * 256;
            int r = lin >> 3, c4 = (lin & 7) << 2;
            cp16(&As[s][r * AS_ST + c4], &A[(size_t)(m0 + r) * Dn + kk + c4]);
        }
        #pragma unroll
        for (int i = 0; i < 4; i++) {
            int lin = tid + i * 256;
            int r = lin >> 5, c4 = (lin & 31) << 2;
            cp16(&Bs[s][r * BS_ST + c4], &W[(size_t)(kk + r) * Dn + n0 + c4]);
        }
        cp_commit();
    };

    issue(0, 0);
    issue(32, 1);

    for (int kstep = 0; kstep < NK; kstep++) {
        const int s = kstep & 1;
        if (kstep + 1 < NK) cp_wait<1>(); else cp_wait<0>();
        __syncthreads();

        #pragma unroll
        for (int ks = 0; ks < 4; ks++) {
            const int k0 = ks * 8;
            uint32_t af[2][4];
            #pragma unroll
            for (int mi = 0; mi < 2; mi++) {
                ldm_x4(af[mi], &As[s][(wm * 32 + mi * 16 + arow) * AS_ST + k0 + acol]);
                #pragma unroll
                for (int j = 0; j < 4; j++) af[mi][j] = u2tf32(af[mi][j]);
            }
            uint32_t bf0[8], bf1[8];
            #pragma unroll
            for (int ni = 0; ni < 8; ni++) {
                int n = wn * 64 + ni * 8 + ln;
                bf0[ni] = f2tf32(Bs[s][(k0 + lk)     * BS_ST + n]);
                bf1[ni] = f2tf32(Bs[s][(k0 + 4 + lk) * BS_ST + n]);
            }
            #pragma unroll
            for (int mi = 0; mi < 2; mi++)
                #pragma unroll
                for (int ni = 0; ni < 8; ni++)
                    mma_tf32(acc[mi][ni], af[mi][0], af[mi][1], af[mi][2], af[mi][3],
                             bf0[ni], bf1[ni]);
        }
        __syncthreads();
        if (kstep + 2 < NK) issue((kstep + 2) * 32, s);
    }

    // epilogue
    #pragma unroll
    for (int mi = 0; mi < 2; mi++) {
        #pragma unroll
        for (int ni = 0; ni < 8; ni++) {
            int n = n0 + wn * 64 + ni * 8 + lk * 2;
            float bb0 = bias[n], bb1 = bias[n + 1];
            #pragma unroll
            for (int rr = 0; rr < 2; rr++) {
                int m = m0 + wm * 32 + mi * 16 + ln + rr * 8;
                float2 o;
                o.x = acc[mi][ni][rr * 2 + 0] + bb0;
                o.y = acc[mi][ni][rr * 2 + 1] + bb1;
                if (SCATTER) {
                    int b = m >> 11, sI = m & (Sn - 1);
                    int h = n >> 6, hd = n & 63;
                    *(float2*)&out[((size_t)(b * Hn + h) * Sn + sI) * HDn + hd] = o;
                } else {
                    *(float2*)&out[(size_t)m * Dn + n] = o;
                }
            }
        }
    }
}

__global__ __launch_bounds__(256, 2)
void qkv_gemm_tc_kernel(const float* __restrict__ x,
                        const float* __restrict__ Wq, const float* __restrict__ bq,
                        const float* __restrict__ Wk, const float* __restrict__ bk,
                        const float* __restrict__ Wv, const float* __restrict__ bv) {
    const float* W; const float* bias; float* out;
    if (blockIdx.z == 0)      { W = Wq; bias = bq; out = g_q; }
    else if (blockIdx.z == 1) { W = Wk; bias = bk; out = g_k; }
    else                      { W = Wv; bias = bv; out = g_v; }
    gemm_tf32_body<1>(x, W, bias, out);
}

__global__ __launch_bounds__(256, 2)
void out_gemm_tc_kernel(const float* __restrict__ Wo,
                        const float* __restrict__ bo,
                        float* __restrict__ out) {
    gemm_tf32_body<0>(g_attn, Wo, bo, out);
}

// ---------------------------------------------------------------------------
// Kernel 3: tensor-core flash attention, 128 q-rows / 8 warps per block,
// cp.async double-buffered K/V tiles (64 keys each).
// Smem: Ps 128x68 (holds raw Q during prologue, then tf32 P),
//       Ks[2] 64x68 raw fp32, Vs[2] 64x72 raw fp32.
// tf32 conversion on register fragments.
// ---------------------------------------------------------------------------
#define QP_ST 68
#define KS_ST 68
#define VS_ST 72
#define ATTN_SMEM_FLOATS (128 * QP_ST + 2 * 64 * KS_ST + 2 * 64 * VS_ST)
#define ATTN_SMEM_BYTES  (ATTN_SMEM_FLOATS * 4)

__global__ __launch_bounds__(256, 1)
void attn_tc_kernel(const int* __restrict__ mask) {
    extern __shared__ float sm[];
    float* Ps = sm;                                 // 128*68
    float* Ks = sm + 128 * QP_ST;                   // 2 * 64*68
    float* Vs = Ks + 2 * 64 * KS_ST;                // 2 * 64*72
    __shared__ int maskS[2][64];

    const int tid  = threadIdx.x;
    const int lane = tid & 31;
    const int warp = tid >> 5;                      // 0..7
    const int q0   = blockIdx.x * 128;
    const int h    = blockIdx.y;
    const int b    = blockIdx.z;

    const float* qb = g_q + ((size_t)(b * Hn + h) * Sn + q0) * HDn;
    const float* kb = g_k + ((size_t)(b * Hn + h) * Sn) * HDn;
    const float* vb = g_v + ((size_t)(b * Hn + h) * Sn) * HDn;
    const float bias  = g_bias[b * Hn + h];
    const float scale = 0.125f;

    const int arow = (lane < 16) ? lane : lane - 16;
    const int acol = (lane < 16) ? 0 : 4;
    const int lk   = lane & 3;
    const int ln   = lane >> 2;

    const int NT = Sn / 64;    // 32 key tiles

    auto issue_kv = [&](int kt, int s) {
        const float* kp = kb + (size_t)kt * 64 * HDn;
        const float* vp = vb + (size_t)kt * 64 * HDn;
        #pragma unroll
        for (int i = 0; i < 4; i++) {
            int lin = tid + i * 256;
            int r = lin >> 4, c4 = (lin & 15) << 2;
            cp16(&Ks[s * 64 * KS_ST + r * KS_ST + c4], kp + (size_t)r * HDn + c4);
            cp16(&Vs[s * 64 * VS_ST + r * VS_ST + c4], vp + (size_t)r * HDn + c4);
        }
        if (tid < 64) maskS[s][tid] = mask[b * Sn + kt * 64 + tid];
        cp_commit();
    };

    // ---- prologue: Q (group 0), KV stage 0 (group 1), KV stage 1 (group 2) ----
    #pragma unroll
    for (int i = 0; i < 8; i++) {
        int lin = tid + i * 256;
        int r = lin >> 4, c4 = (lin & 15) << 2;
        cp16(&Ps[r * QP_ST + c4], qb + (size_t)r * HDn + c4);
    }
    cp_commit();
    issue_kv(0, 0);
    issue_kv(1, 1);

    cp_wait<2>();          // Q arrived
    __syncthreads();

    // Q fragments -> tf32 registers, held for whole kernel
    uint32_t qf[8][4];
    #pragma unroll
    for (int ks = 0; ks < 8; ks++) {
        ldm_x4(qf[ks], &Ps[(warp * 16 + arow) * QP_ST + ks * 8 + acol]);
        #pragma unroll
        for (int j = 0; j < 4; j++) qf[ks][j] = u2tf32(qf[ks][j]);
    }
    __syncthreads();       // everyone done reading Q; Ps becomes P storage

    float o[8][4] = {};
    float m_i[2] = {-1e30f, -1e30f};
    float l_i[2] = {0.0f, 0.0f};

    for (int kt = 0; kt < NT; kt++) {
        const int s = kt & 1;
        if (kt + 1 < NT) cp_wait<1>(); else cp_wait<0>();
        __syncthreads();

        const float* KsS = Ks + s * 64 * KS_ST;
        const float* VsS = Vs + s * 64 * VS_ST;

        // ---- S = Q @ K^T ----
        float sacc[8][4] = {};
        #pragma unroll
        for (int ks = 0; ks < 8; ks++) {
            #pragma unroll
            for (int ni = 0; ni < 8; ni++) {
                uint32_t b0 = f2tf32(KsS[(ni * 8 + ln) * KS_ST + ks * 8 + lk]);
                uint32_t b1 = f2tf32(KsS[(ni * 8 + ln) * KS_ST + ks * 8 + 4 + lk]);
                mma_tf32(sacc[ni], qf[ks][0], qf[ks][1], qf[ks][2], qf[ks][3], b0, b1);
            }
        }

        // ---- online softmax on C-fragments; write P (tf32) into Ps ----
        #pragma unroll
        for (int rr = 0; rr < 2; rr++) {
            float sv[8][2];
            float mx = -1e30f;
            #pragma unroll
            for (int ni = 0; ni < 8; ni++) {
                int c = ni * 8 + lk * 2;
                float s0 = maskS[s][c]     ? sacc[ni][rr * 2 + 0] * scale + bias : -1e30f;
                float s1 = maskS[s][c + 1] ? sacc[ni][rr * 2 + 1] * scale + bias : -1e30f;
                sv[ni][0] = s0; sv[ni][1] = s1;
                mx = fmaxf(mx, fmaxf(s0, s1));
            }
            mx = fmaxf(mx, __shfl_xor_sync(0xffffffffu, mx, 1));
            mx = fmaxf(mx, __shfl_xor_sync(0xffffffffu, mx, 2));
            float m_new = fmaxf(m_i[rr], mx);

            float rs = 0.0f;
            int prow = (warp * 16 + ln + rr * 8) * QP_ST;
            #pragma unroll
            for (int ni = 0; ni < 8; ni++) {
                float p0 = __expf(sv[ni][0] - m_new);
                float p1 = __expf(sv[ni][1] - m_new);
                rs += p0 + p1;
                float2 pp;
                pp.x = __uint_as_float(f2tf32(p0));
                pp.y = __uint_as_float(f2tf32(p1));
                *(float2*)&Ps[prow + ni * 8 + lk * 2] = pp;
            }
            rs += __shfl_xor_sync(0xffffffffu, rs, 1);
            rs += __shfl_xor_sync(0xffffffffu, rs, 2);

            float alpha = __expf(m_i[rr] - m_new);
            l_i[rr] = l_i[rr] * alpha + rs;
            m_i[rr] = m_new;
            #pragma unroll
            for (int ni = 0; ni < 8; ni++) {
                o[ni][rr * 2 + 0] *= alpha;
                o[ni][rr * 2 + 1] *= alpha;
            }
        }
        __syncwarp();   // per-warp P rows: STS -> ldmatrix ordering

        // ---- O += P @ V ----
        #pragma unroll
        for (int ks = 0; ks < 8; ks++) {
            uint32_t pf[4];
            ldm_x4(pf, &Ps[(warp * 16 + arow) * QP_ST + ks * 8 + acol]);
            #pragma unroll
            for (int ni = 0; ni < 8; ni++) {
                uint32_t b0 = f2tf32(VsS[(ks * 8 + lk)     * VS_ST + ni * 8 + ln]);
                uint32_t b1 = f2tf32(VsS[(ks * 8 + 4 + lk) * VS_ST + ni * 8 + ln]);
                mma_tf32(o[ni], pf[0], pf[1], pf[2], pf[3], b0, b1);
            }
        }

        __syncthreads();               // all warps done with stage s buffers
        if (kt + 2 < NT) issue_kv(kt + 2, s);
    }

    // ---- finalize, write [B,S,D] ----
    #pragma unroll
    for (int rr = 0; rr < 2; rr++) {
        float inv = 1.0f / l_i[rr];
        int q = q0 + warp * 16 + ln + rr * 8;
        #pragma unroll
        for (int ni = 0; ni < 8; ni++) {
            float2 ov;
            ov.x = o[ni][rr * 2 + 0] * inv;
            ov.y = o[ni][rr * 2 + 1] * inv;
            *(float2*)&g_attn[((size_t)(b * Sn + q)) * Dn + h * HDn + ni * 8 + lk * 2] = ov;
        }
    }
}

// ---------------------------------------------------------------------------
// Launch
// ---------------------------------------------------------------------------
extern "C" void kernel_launch(void* const* d_in, const int* in_sizes, int n_in,
                              void* d_out, int out_size) {
    const float* x    = (const float*)d_in[0];
    const float* te   = (const float*)d_in[1];
    const int*   mask = (const int*)  d_in[2];
    const float* Wq   = (const float*)d_in[3];
    const float* bq   = (const float*)d_in[4];
    const float* Wk   = (const float*)d_in[5];
    const float* bk   = (const float*)d_in[6];
    const float* Wv   = (const float*)d_in[7];
    const float* bv   = (const float*)d_in[8];
    const float* Wo   = (const float*)d_in[9];
    const float* bo   = (const float*)d_in[10];
    const float* Wt   = (const float*)d_in[11];
    const float* bt   = (const float*)d_in[12];
    float* out = (float*)d_out;

    (void)in_sizes; (void)n_in; (void)out_size;

    cudaFuncSetAttribute(attn_tc_kernel,
                         cudaFuncAttributeMaxDynamicSharedMemorySize,
                         ATTN_SMEM_BYTES);

    task_bias_kernel<<<1, 64>>>(te, Wt, bt);
    qkv_gemm_tc_kernel<<<dim3(Dn / 128, Mn / 128, 3), 256>>>(x, Wq, bq, Wk, bk, Wv, bv);
    attn_tc_kernel<<<dim3(Sn / 128, Hn, Bn), 256, ATTN_SMEM_BYTES>>>(mask);
    out_gemm_tc_kernel<<<dim3(Dn / 128, Mn / 128, 1), 256>>>(Wo, bo, out);
}